// round 10
// baseline (speedup 1.0000x reference)
#include <cuda_runtime.h>
#include <math.h>

#define NODES 100000
#define NEDGES 3200000
#define INC 512
#define HIDC 256
#define OUTC 16
#define KITER 10
#define SCAN_B 1024
#define NSCANB ((NODES + SCAN_B - 1) / SCAN_B)   // 98

// ---------------- scratch (static device globals; no allocation) ----------------
__device__ __align__(16) float g_h0[NODES * OUTC];   // unscaled MLP output
__device__ __align__(16) float g_hA[NODES * OUTC];   // scaled h' ping
__device__ __align__(16) float g_hB[NODES * OUTC];   // scaled h' pong
__device__ float g_dinv[NODES];
__device__ int   g_deg[NODES];
__device__ int   g_cnt[NODES];
__device__ int   g_rexcl[NODES];
__device__ int   g_bsum[NSCANB];
__device__ int   g_boff[NSCANB];
__device__ int   g_rowptr[NODES + 1];
__device__ int   g_src[NEDGES];
__device__ int   g_dst[NEDGES];
__device__ int   g_csrc[NEDGES];       // CSR: src ids grouped by dst
__device__ int   g_is64;

__device__ __forceinline__ void red_add_f4(float* addr, float4 v) {
    asm volatile("red.global.add.v4.f32 [%0], {%1, %2, %3, %4};"
                 :: "l"(addr), "f"(v.x), "f"(v.y), "f"(v.z), "f"(v.w)
                 : "memory");
}

__device__ __forceinline__ unsigned tf32_of(float v) {
    unsigned r;
    asm("cvt.rna.tf32.f32 %0, %1;" : "=r"(r) : "f"(v));
    return r;
}

// scaled buffers only (1 = hA, 2 = hB)
__device__ __forceinline__ const float4* sel_in(int s) {
    return (const float4*)(s == 1 ? g_hA : g_hB);
}
__device__ __forceinline__ float4* sel_out(int s) {
    return (float4*)(s == 1 ? g_hA : g_hB);
}

// ---------------- dtype detection for edge_index (int32 vs int64) ----------------
__global__ void detect_kernel(const int* __restrict__ ei32) {
    if (threadIdx.x == 0 && blockIdx.x == 0) {
        int s = 0;
#pragma unroll
        for (int i = 0; i < 64; i++) s |= ei32[2 * i + 1];
        g_is64 = (s == 0) ? 1 : 0;
    }
}

// ---------------- init ----------------
__global__ void zero_kernel() {
    int i = blockIdx.x * blockDim.x + threadIdx.x;
    if (i < NODES * OUTC) g_h0[i] = 0.f;
    if (i < NODES) { g_deg[i] = 0; g_cnt[i] = 0; }
}

// ---------------- edge prep ----------------
__global__ void edge_kernel(const void* __restrict__ ei) {
    int e = blockIdx.x * blockDim.x + threadIdx.x;
    if (e >= NEDGES) return;
    int s, d;
    if (g_is64) {
        const long long* p = (const long long*)ei;
        s = (int)p[e];
        d = (int)p[NEDGES + e];
    } else {
        const int* p = (const int*)ei;
        s = p[e];
        d = p[NEDGES + e];
    }
    g_src[e] = s;
    g_dst[e] = d;
    atomicAdd(&g_deg[d], 1);
}

// ---------------- exclusive scan of deg -> rowptr ----------------
__global__ __launch_bounds__(SCAN_B) void scanA_kernel() {
    __shared__ int s[SCAN_B];
    int tid = threadIdx.x;
    int i = blockIdx.x * SCAN_B + tid;
    int v = (i < NODES) ? g_deg[i] : 0;
    s[tid] = v;
    __syncthreads();
#pragma unroll
    for (int off = 1; off < SCAN_B; off <<= 1) {
        int t = (tid >= off) ? s[tid - off] : 0;
        __syncthreads();
        s[tid] += t;
        __syncthreads();
    }
    if (i < NODES) g_rexcl[i] = s[tid] - v;
    if (tid == SCAN_B - 1) g_bsum[blockIdx.x] = s[tid];
}

__global__ __launch_bounds__(128) void scanB_kernel() {
    __shared__ int s[128];
    int tid = threadIdx.x;
    int v = (tid < NSCANB) ? g_bsum[tid] : 0;
    s[tid] = v;
    __syncthreads();
#pragma unroll
    for (int off = 1; off < 128; off <<= 1) {
        int t = (tid >= off) ? s[tid - off] : 0;
        __syncthreads();
        s[tid] += t;
        __syncthreads();
    }
    if (tid < NSCANB) g_boff[tid] = s[tid] - v;   // exclusive
    if (tid == 0) g_rowptr[NODES] = NEDGES;
}

__global__ void scanC_kernel() {
    int i = blockIdx.x * blockDim.x + threadIdx.x;
    if (i >= NODES) return;
    g_rowptr[i] = g_rexcl[i] + g_boff[i >> 10];
}

__global__ void dinv_kernel() {
    int i = blockIdx.x * blockDim.x + threadIdx.x;
    if (i >= NODES) return;
    g_dinv[i] = rsqrtf((float)g_deg[i] + 1.0f);   // +1 = self loop
}

// counting-sort placement: group src by dst
__global__ void place_kernel() {
    int e = blockIdx.x * blockDim.x + threadIdx.x;
    if (e >= NEDGES) return;
    int d = g_dst[e];
    int pos = g_rowptr[d] + atomicAdd(&g_cnt[d], 1);
    g_csrc[pos] = g_src[e];
}

// h'_init = dinv * h0
__global__ void prescale_kernel() {
    int t = blockIdx.x * blockDim.x + threadIdx.x;
    if (t >= NODES * 4) return;
    float di = g_dinv[t >> 2];
    float4 h = ((const float4*)g_h0)[t];
    ((float4*)g_hA)[t] = make_float4(di * h.x, di * h.y, di * h.z, di * h.w);
}

// ---------------- fused MLP via tf32 tensor cores ----------------
#define BM 128
#define BN 64
#define BKK 32
#define XS_STRIDE 136
#define WS_STRIDE 72

__global__ __launch_bounds__(256) void mlp_tc_kernel(
    const float* __restrict__ x, const float* __restrict__ W1,
    const float* __restrict__ b1, const float* __restrict__ W2,
    const float* __restrict__ b2)
{
    __shared__ __align__(16) float sm[9344];
    float* Xt = sm;                       // [BKK][XS_STRIDE]
    float* Ws = sm + BKK * XS_STRIDE;     // [BKK][WS_STRIDE]

    const int tid  = threadIdx.x;
    const int lane = tid & 31;
    const int wid  = tid >> 5;
    const int warp_m = wid >> 1;
    const int warp_n = wid & 1;
    const int bm = blockIdx.x * BM;
    const int bn = blockIdx.y * BN;
    const int gID = lane >> 2;
    const int tig = lane & 3;

    float acc[2][4][4];
#pragma unroll
    for (int mt = 0; mt < 2; mt++)
#pragma unroll
        for (int nt = 0; nt < 4; nt++)
#pragma unroll
            for (int v = 0; v < 4; v++) acc[mt][nt][v] = 0.f;

    for (int k0 = 0; k0 < INC; k0 += BKK) {
#pragma unroll
        for (int it = 0; it < 4; it++) {
            int l  = tid + it * 256;
            int r  = l & 127;
            int kq = l >> 7;
            int gm = bm + r;
            float4 v = make_float4(0.f, 0.f, 0.f, 0.f);
            if (gm < NODES) v = *(const float4*)(x + (size_t)gm * INC + k0 + kq * 4);
            ((unsigned*)Xt)[(kq * 4 + 0) * XS_STRIDE + r] = tf32_of(v.x);
            ((unsigned*)Xt)[(kq * 4 + 1) * XS_STRIDE + r] = tf32_of(v.y);
            ((unsigned*)Xt)[(kq * 4 + 2) * XS_STRIDE + r] = tf32_of(v.z);
            ((unsigned*)Xt)[(kq * 4 + 3) * XS_STRIDE + r] = tf32_of(v.w);
        }
#pragma unroll
        for (int it = 0; it < 2; it++) {
            int l  = tid + it * 256;
            int kr = l >> 4;
            int nq = l & 15;
            float4 w = *(const float4*)(W1 + (size_t)(k0 + kr) * HIDC + bn + nq * 4);
            uint4 t;
            t.x = tf32_of(w.x); t.y = tf32_of(w.y);
            t.z = tf32_of(w.z); t.w = tf32_of(w.w);
            *(uint4*)((unsigned*)Ws + kr * WS_STRIDE + nq * 4) = t;
        }
        __syncthreads();

#pragma unroll
        for (int ks = 0; ks < 4; ks++) {
            const int kb = ks * 8;
            unsigned a[2][4], b[4][2];
#pragma unroll
            for (int mt = 0; mt < 2; mt++) {
                int m = warp_m * 32 + mt * 16 + gID;
                const unsigned* X32 = (const unsigned*)Xt;
                a[mt][0] = X32[(kb + tig) * XS_STRIDE + m];
                a[mt][1] = X32[(kb + tig) * XS_STRIDE + m + 8];
                a[mt][2] = X32[(kb + tig + 4) * XS_STRIDE + m];
                a[mt][3] = X32[(kb + tig + 4) * XS_STRIDE + m + 8];
            }
#pragma unroll
            for (int nt = 0; nt < 4; nt++) {
                int n = warp_n * 32 + nt * 8 + gID;
                const unsigned* W32 = (const unsigned*)Ws;
                b[nt][0] = W32[(kb + tig) * WS_STRIDE + n];
                b[nt][1] = W32[(kb + tig + 4) * WS_STRIDE + n];
            }
#pragma unroll
            for (int mt = 0; mt < 2; mt++)
#pragma unroll
                for (int nt = 0; nt < 4; nt++) {
                    float* c = acc[mt][nt];
                    asm volatile(
                        "mma.sync.aligned.m16n8k8.row.col.f32.tf32.tf32.f32 "
                        "{%0,%1,%2,%3}, {%4,%5,%6,%7}, {%8,%9}, {%0,%1,%2,%3};"
                        : "+f"(c[0]), "+f"(c[1]), "+f"(c[2]), "+f"(c[3])
                        : "r"(a[mt][0]), "r"(a[mt][1]), "r"(a[mt][2]), "r"(a[mt][3]),
                          "r"(b[nt][0]), "r"(b[nt][1]));
                }
        }
        __syncthreads();
    }

    // epilogue: bias + relu -> smem tile [128][65]
    float* tile = sm;
    float* W2s  = sm + BM * 65;

#pragma unroll
    for (int mt = 0; mt < 2; mt++) {
        int r0 = warp_m * 32 + mt * 16 + gID;
        int r1 = r0 + 8;
#pragma unroll
        for (int nt = 0; nt < 4; nt++) {
            int c0 = warp_n * 32 + nt * 8 + 2 * tig;
            int c1 = c0 + 1;
            float bc0 = b1[bn + c0];
            float bc1 = b1[bn + c1];
            float v00 = acc[mt][nt][0] + bc0;
            float v01 = acc[mt][nt][1] + bc1;
            float v10 = acc[mt][nt][2] + bc0;
            float v11 = acc[mt][nt][3] + bc1;
            tile[r0 * 65 + c0] = v00 > 0.f ? v00 : 0.f;
            tile[r0 * 65 + c1] = v01 > 0.f ? v01 : 0.f;
            tile[r1 * 65 + c0] = v10 > 0.f ? v10 : 0.f;
            tile[r1 * 65 + c1] = v11 > 0.f ? v11 : 0.f;
        }
    }
    {
        int rr = tid >> 2;
        int cc = (tid & 3) * 4;
        *(float4*)(W2s + rr * OUTC + cc) =
            *(const float4*)(W2 + (size_t)(bn + rr) * OUTC + cc);
    }
    __syncthreads();

    int m2 = tid >> 1;
    int ch = (tid & 1) * 8;
    float acc2[8];
#pragma unroll
    for (int c = 0; c < 8; c++) acc2[c] = (blockIdx.y == 0) ? b2[ch + c] : 0.f;
#pragma unroll 8
    for (int k = 0; k < BN; k++) {
        float v = tile[m2 * 65 + k];
        float4 w0 = *(float4*)(W2s + k * OUTC + ch);
        float4 w1 = *(float4*)(W2s + k * OUTC + ch + 4);
        acc2[0] += v * w0.x; acc2[1] += v * w0.y;
        acc2[2] += v * w0.z; acc2[3] += v * w0.w;
        acc2[4] += v * w1.x; acc2[5] += v * w1.y;
        acc2[6] += v * w1.z; acc2[7] += v * w1.w;
    }
    int gm2 = bm + m2;
    if (gm2 < NODES) {
        red_add_f4(g_h0 + (size_t)gm2 * OUTC + ch,
                   make_float4(acc2[0], acc2[1], acc2[2], acc2[3]));
        red_add_f4(g_h0 + (size_t)gm2 * OUTC + ch + 4,
                   make_float4(acc2[4], acc2[5], acc2[6], acc2[7]));
    }
}

// ---------------- propagation: warp-per-node CSR gather, predicated x4 batches ----------------
// lane = e_local*4 + q. Every batch covers 32 edges; per-edge predicate masks
// OOB slots (no serial tail => MLP=4 for ALL edges).
// Reduce via shfl_xor(4,8,16). o = 0.9*di*(sum + h'[i]) + 0.1*h0[i].
__global__ __launch_bounds__(256) void gather_kernel(int sin, int sout, int final_,
                                                     float* __restrict__ out) {
    int w = (blockIdx.x * blockDim.x + threadIdx.x) >> 5;   // node id
    if (w >= NODES) return;
    const int lane = threadIdx.x & 31;
    const int el   = lane >> 2;    // 0..7  edge slot
    const int q    = lane & 3;     // 0..3  channel quad
    const float4* __restrict__ hin = sel_in(sin);
    const int* __restrict__ csrc = g_csrc;
    const int end = g_rowptr[w + 1];

    float4 a0 = make_float4(0.f, 0.f, 0.f, 0.f);
    float4 a1 = make_float4(0.f, 0.f, 0.f, 0.f);
    for (int eb = g_rowptr[w] + el; eb < end; eb += 32) {
        int e0 = eb, e1 = eb + 8, e2 = eb + 16, e3 = eb + 24;
        bool p1 = e1 < end, p2 = e2 < end, p3 = e3 < end;
        int s0 = __ldg(&csrc[e0]);
        int s1 = p1 ? __ldg(&csrc[e1]) : 0;
        int s2 = p2 ? __ldg(&csrc[e2]) : 0;
        int s3 = p3 ? __ldg(&csrc[e3]) : 0;
        float4 v0 = hin[s0 * 4 + q];
        float4 v1 = p1 ? hin[s1 * 4 + q] : make_float4(0.f, 0.f, 0.f, 0.f);
        float4 v2 = p2 ? hin[s2 * 4 + q] : make_float4(0.f, 0.f, 0.f, 0.f);
        float4 v3 = p3 ? hin[s3 * 4 + q] : make_float4(0.f, 0.f, 0.f, 0.f);
        a0.x += v0.x + v1.x; a0.y += v0.y + v1.y;
        a0.z += v0.z + v1.z; a0.w += v0.w + v1.w;
        a1.x += v2.x + v3.x; a1.y += v2.y + v3.y;
        a1.z += v2.z + v3.z; a1.w += v2.w + v3.w;
    }
    float4 acc = make_float4(a0.x + a1.x, a0.y + a1.y, a0.z + a1.z, a0.w + a1.w);
    // sum the 8 edge slots (lanes with same q)
#pragma unroll
    for (int off = 4; off <= 16; off <<= 1) {
        acc.x += __shfl_xor_sync(0xFFFFFFFFu, acc.x, off);
        acc.y += __shfl_xor_sync(0xFFFFFFFFu, acc.y, off);
        acc.z += __shfl_xor_sync(0xFFFFFFFFu, acc.z, off);
        acc.w += __shfl_xor_sync(0xFFFFFFFFu, acc.w, off);
    }

    float di = g_dinv[w];
    float4 hs  = hin[w * 4 + q];                 // h'[i] (scaled self)
    float4 h0v = ((const float4*)g_h0)[w * 4 + q];
    float4 o;
    o.x = 0.9f * di * (acc.x + hs.x) + 0.1f * h0v.x;
    o.y = 0.9f * di * (acc.y + hs.y) + 0.1f * h0v.y;
    o.z = 0.9f * di * (acc.z + hs.z) + 0.1f * h0v.z;
    o.w = 0.9f * di * (acc.w + hs.w) + 0.1f * h0v.w;

    if (!final_) {
        if (el == 0)
            sel_out(sout)[w * 4 + q] =
                make_float4(di * o.x, di * o.y, di * o.z, di * o.w);
    } else {
        float m = fmaxf(fmaxf(o.x, o.y), fmaxf(o.z, o.w));
        m = fmaxf(m, __shfl_xor_sync(0xFFFFFFFFu, m, 1));
        m = fmaxf(m, __shfl_xor_sync(0xFFFFFFFFu, m, 2));
        float ssum = expf(o.x - m) + expf(o.y - m) + expf(o.z - m) + expf(o.w - m);
        ssum += __shfl_xor_sync(0xFFFFFFFFu, ssum, 1);
        ssum += __shfl_xor_sync(0xFFFFFFFFu, ssum, 2);
        float ls = logf(ssum) + m;
        if (el == 0)
            ((float4*)out)[w * 4 + q] =
                make_float4(o.x - ls, o.y - ls, o.z - ls, o.w - ls);
    }
}

// ---------------- launch ----------------
extern "C" void kernel_launch(void* const* d_in, const int* in_sizes, int n_in,
                              void* d_out, int out_size)
{
    const float* x  = (const float*)d_in[0];
    const void* ei  = d_in[1];
    const float* W1 = (const float*)d_in[2];
    const float* b1 = (const float*)d_in[3];
    const float* W2 = (const float*)d_in[4];
    const float* b2 = (const float*)d_in[5];
    float* out      = (float*)d_out;

    detect_kernel<<<1, 32>>>((const int*)ei);
    zero_kernel<<<(NODES * OUTC + 255) / 256, 256>>>();
    edge_kernel<<<(NEDGES + 255) / 256, 256>>>(ei);
    scanA_kernel<<<NSCANB, SCAN_B>>>();
    scanB_kernel<<<1, 128>>>();
    scanC_kernel<<<(NODES + 255) / 256, 256>>>();
    dinv_kernel<<<(NODES + 255) / 256, 256>>>();
    place_kernel<<<(NEDGES + 255) / 256, 256>>>();
    mlp_tc_kernel<<<dim3((NODES + BM - 1) / BM, HIDC / BN), 256>>>(x, W1, b1, W2, b2);
    prescale_kernel<<<(NODES * 4 + 255) / 256, 256>>>();

    int cur = 1;
    for (int t = 0; t < KITER; t++) {
        int nxt = (cur == 1) ? 2 : 1;
        int fin = (t == KITER - 1) ? 1 : 0;
        gather_kernel<<<(NODES * 32 + 255) / 256, 256>>>(cur, nxt, fin, out);
        cur = nxt;
    }
}

// round 11
// speedup vs baseline: 1.0187x; 1.0187x over previous
#include <cuda_runtime.h>
#include <cuda_fp16.h>
#include <math.h>

#define NODES 100000
#define NEDGES 3200000
#define INC 512
#define HIDC 256
#define OUTC 16
#define KITER 10
#define SCAN_B 1024
#define NSCANB ((NODES + SCAN_B - 1) / SCAN_B)   // 98

// ---------------- scratch (static device globals; no allocation) ----------------
__device__ __align__(16) float  g_h0[NODES * OUTC];   // unscaled MLP output (fp32)
__device__ __align__(16) __half g_pA[NODES * OUTC];   // scaled h' ping (fp16)
__device__ __align__(16) __half g_pB[NODES * OUTC];   // scaled h' pong (fp16)
__device__ float g_dinv[NODES];
__device__ int   g_deg[NODES];
__device__ int   g_cnt[NODES];
__device__ int   g_rexcl[NODES];
__device__ int   g_bsum[NSCANB];
__device__ int   g_boff[NSCANB];
__device__ int   g_rowptr[NODES + 1];
__device__ int   g_src[NEDGES];
__device__ int   g_dst[NEDGES];
__device__ int   g_csrc[NEDGES];       // CSR: src ids grouped by dst
__device__ int   g_is64;

__device__ __forceinline__ void red_add_f4(float* addr, float4 v) {
    asm volatile("red.global.add.v4.f32 [%0], {%1, %2, %3, %4};"
                 :: "l"(addr), "f"(v.x), "f"(v.y), "f"(v.z), "f"(v.w)
                 : "memory");
}

__device__ __forceinline__ unsigned tf32_of(float v) {
    unsigned r;
    asm("cvt.rna.tf32.f32 %0, %1;" : "=r"(r) : "f"(v));
    return r;
}

__device__ __forceinline__ float4 h4_to_f4(uint2 u) {
    __half2 h0 = *reinterpret_cast<__half2*>(&u.x);
    __half2 h1 = *reinterpret_cast<__half2*>(&u.y);
    float2 f0 = __half22float2(h0);
    float2 f1 = __half22float2(h1);
    return make_float4(f0.x, f0.y, f1.x, f1.y);
}

__device__ __forceinline__ uint2 f4_to_h4(float4 v) {
    __half2 h0 = __floats2half2_rn(v.x, v.y);
    __half2 h1 = __floats2half2_rn(v.z, v.w);
    uint2 u;
    u.x = *reinterpret_cast<unsigned*>(&h0);
    u.y = *reinterpret_cast<unsigned*>(&h1);
    return u;
}

// fp16 buffers (1 = pA, 2 = pB); index unit = uint2 (4 halves = one channel quad)
__device__ __forceinline__ const uint2* sel_in(int s) {
    return (const uint2*)(s == 1 ? g_pA : g_pB);
}
__device__ __forceinline__ uint2* sel_out(int s) {
    return (uint2*)(s == 1 ? g_pA : g_pB);
}

// ---------------- dtype detection for edge_index (int32 vs int64) ----------------
__global__ void detect_kernel(const int* __restrict__ ei32) {
    if (threadIdx.x == 0 && blockIdx.x == 0) {
        int s = 0;
#pragma unroll
        for (int i = 0; i < 64; i++) s |= ei32[2 * i + 1];
        g_is64 = (s == 0) ? 1 : 0;
    }
}

// ---------------- init ----------------
__global__ void zero_kernel() {
    int i = blockIdx.x * blockDim.x + threadIdx.x;
    if (i < NODES * OUTC) g_h0[i] = 0.f;
    if (i < NODES) { g_deg[i] = 0; g_cnt[i] = 0; }
}

// ---------------- edge prep ----------------
__global__ void edge_kernel(const void* __restrict__ ei) {
    int e = blockIdx.x * blockDim.x + threadIdx.x;
    if (e >= NEDGES) return;
    int s, d;
    if (g_is64) {
        const long long* p = (const long long*)ei;
        s = (int)p[e];
        d = (int)p[NEDGES + e];
    } else {
        const int* p = (const int*)ei;
        s = p[e];
        d = p[NEDGES + e];
    }
    g_src[e] = s;
    g_dst[e] = d;
    atomicAdd(&g_deg[d], 1);
}

// ---------------- exclusive scan of deg -> rowptr ----------------
__global__ __launch_bounds__(SCAN_B) void scanA_kernel() {
    __shared__ int s[SCAN_B];
    int tid = threadIdx.x;
    int i = blockIdx.x * SCAN_B + tid;
    int v = (i < NODES) ? g_deg[i] : 0;
    s[tid] = v;
    __syncthreads();
#pragma unroll
    for (int off = 1; off < SCAN_B; off <<= 1) {
        int t = (tid >= off) ? s[tid - off] : 0;
        __syncthreads();
        s[tid] += t;
        __syncthreads();
    }
    if (i < NODES) g_rexcl[i] = s[tid] - v;
    if (tid == SCAN_B - 1) g_bsum[blockIdx.x] = s[tid];
}

__global__ __launch_bounds__(128) void scanB_kernel() {
    __shared__ int s[128];
    int tid = threadIdx.x;
    int v = (tid < NSCANB) ? g_bsum[tid] : 0;
    s[tid] = v;
    __syncthreads();
#pragma unroll
    for (int off = 1; off < 128; off <<= 1) {
        int t = (tid >= off) ? s[tid - off] : 0;
        __syncthreads();
        s[tid] += t;
        __syncthreads();
    }
    if (tid < NSCANB) g_boff[tid] = s[tid] - v;   // exclusive
    if (tid == 0) g_rowptr[NODES] = NEDGES;
}

__global__ void scanC_kernel() {
    int i = blockIdx.x * blockDim.x + threadIdx.x;
    if (i >= NODES) return;
    g_rowptr[i] = g_rexcl[i] + g_boff[i >> 10];
}

__global__ void dinv_kernel() {
    int i = blockIdx.x * blockDim.x + threadIdx.x;
    if (i >= NODES) return;
    g_dinv[i] = rsqrtf((float)g_deg[i] + 1.0f);   // +1 = self loop
}

// counting-sort placement: group src by dst
__global__ void place_kernel() {
    int e = blockIdx.x * blockDim.x + threadIdx.x;
    if (e >= NEDGES) return;
    int d = g_dst[e];
    int pos = g_rowptr[d] + atomicAdd(&g_cnt[d], 1);
    g_csrc[pos] = g_src[e];
}

// h'_init = fp16(dinv * h0)
__global__ void prescale_kernel() {
    int t = blockIdx.x * blockDim.x + threadIdx.x;
    if (t >= NODES * 4) return;
    float di = g_dinv[t >> 2];
    float4 h = ((const float4*)g_h0)[t];
    ((uint2*)g_pA)[t] = f4_to_h4(make_float4(di * h.x, di * h.y, di * h.z, di * h.w));
}

// ---------------- fused MLP via tf32 tensor cores ----------------
#define BM 128
#define BN 64
#define BKK 32
#define XS_STRIDE 136
#define WS_STRIDE 72

__global__ __launch_bounds__(256) void mlp_tc_kernel(
    const float* __restrict__ x, const float* __restrict__ W1,
    const float* __restrict__ b1, const float* __restrict__ W2,
    const float* __restrict__ b2)
{
    __shared__ __align__(16) float sm[9344];
    float* Xt = sm;                       // [BKK][XS_STRIDE]
    float* Ws = sm + BKK * XS_STRIDE;     // [BKK][WS_STRIDE]

    const int tid  = threadIdx.x;
    const int lane = tid & 31;
    const int wid  = tid >> 5;
    const int warp_m = wid >> 1;
    const int warp_n = wid & 1;
    const int bm = blockIdx.x * BM;
    const int bn = blockIdx.y * BN;
    const int gID = lane >> 2;
    const int tig = lane & 3;

    float acc[2][4][4];
#pragma unroll
    for (int mt = 0; mt < 2; mt++)
#pragma unroll
        for (int nt = 0; nt < 4; nt++)
#pragma unroll
            for (int v = 0; v < 4; v++) acc[mt][nt][v] = 0.f;

    for (int k0 = 0; k0 < INC; k0 += BKK) {
#pragma unroll
        for (int it = 0; it < 4; it++) {
            int l  = tid + it * 256;
            int r  = l & 127;
            int kq = l >> 7;
            int gm = bm + r;
            float4 v = make_float4(0.f, 0.f, 0.f, 0.f);
            if (gm < NODES) v = *(const float4*)(x + (size_t)gm * INC + k0 + kq * 4);
            ((unsigned*)Xt)[(kq * 4 + 0) * XS_STRIDE + r] = tf32_of(v.x);
            ((unsigned*)Xt)[(kq * 4 + 1) * XS_STRIDE + r] = tf32_of(v.y);
            ((unsigned*)Xt)[(kq * 4 + 2) * XS_STRIDE + r] = tf32_of(v.z);
            ((unsigned*)Xt)[(kq * 4 + 3) * XS_STRIDE + r] = tf32_of(v.w);
        }
#pragma unroll
        for (int it = 0; it < 2; it++) {
            int l  = tid + it * 256;
            int kr = l >> 4;
            int nq = l & 15;
            float4 w = *(const float4*)(W1 + (size_t)(k0 + kr) * HIDC + bn + nq * 4);
            uint4 t;
            t.x = tf32_of(w.x); t.y = tf32_of(w.y);
            t.z = tf32_of(w.z); t.w = tf32_of(w.w);
            *(uint4*)((unsigned*)Ws + kr * WS_STRIDE + nq * 4) = t;
        }
        __syncthreads();

#pragma unroll
        for (int ks = 0; ks < 4; ks++) {
            const int kb = ks * 8;
            unsigned a[2][4], b[4][2];
#pragma unroll
            for (int mt = 0; mt < 2; mt++) {
                int m = warp_m * 32 + mt * 16 + gID;
                const unsigned* X32 = (const unsigned*)Xt;
                a[mt][0] = X32[(kb + tig) * XS_STRIDE + m];
                a[mt][1] = X32[(kb + tig) * XS_STRIDE + m + 8];
                a[mt][2] = X32[(kb + tig + 4) * XS_STRIDE + m];
                a[mt][3] = X32[(kb + tig + 4) * XS_STRIDE + m + 8];
            }
#pragma unroll
            for (int nt = 0; nt < 4; nt++) {
                int n = warp_n * 32 + nt * 8 + gID;
                const unsigned* W32 = (const unsigned*)Ws;
                b[nt][0] = W32[(kb + tig) * WS_STRIDE + n];
                b[nt][1] = W32[(kb + tig + 4) * WS_STRIDE + n];
            }
#pragma unroll
            for (int mt = 0; mt < 2; mt++)
#pragma unroll
                for (int nt = 0; nt < 4; nt++) {
                    float* c = acc[mt][nt];
                    asm volatile(
                        "mma.sync.aligned.m16n8k8.row.col.f32.tf32.tf32.f32 "
                        "{%0,%1,%2,%3}, {%4,%5,%6,%7}, {%8,%9}, {%0,%1,%2,%3};"
                        : "+f"(c[0]), "+f"(c[1]), "+f"(c[2]), "+f"(c[3])
                        : "r"(a[mt][0]), "r"(a[mt][1]), "r"(a[mt][2]), "r"(a[mt][3]),
                          "r"(b[nt][0]), "r"(b[nt][1]));
                }
        }
        __syncthreads();
    }

    // epilogue: bias + relu -> smem tile [128][65]
    float* tile = sm;
    float* W2s  = sm + BM * 65;

#pragma unroll
    for (int mt = 0; mt < 2; mt++) {
        int r0 = warp_m * 32 + mt * 16 + gID;
        int r1 = r0 + 8;
#pragma unroll
        for (int nt = 0; nt < 4; nt++) {
            int c0 = warp_n * 32 + nt * 8 + 2 * tig;
            int c1 = c0 + 1;
            float bc0 = b1[bn + c0];
            float bc1 = b1[bn + c1];
            float v00 = acc[mt][nt][0] + bc0;
            float v01 = acc[mt][nt][1] + bc1;
            float v10 = acc[mt][nt][2] + bc0;
            float v11 = acc[mt][nt][3] + bc1;
            tile[r0 * 65 + c0] = v00 > 0.f ? v00 : 0.f;
            tile[r0 * 65 + c1] = v01 > 0.f ? v01 : 0.f;
            tile[r1 * 65 + c0] = v10 > 0.f ? v10 : 0.f;
            tile[r1 * 65 + c1] = v11 > 0.f ? v11 : 0.f;
        }
    }
    {
        int rr = tid >> 2;
        int cc = (tid & 3) * 4;
        *(float4*)(W2s + rr * OUTC + cc) =
            *(const float4*)(W2 + (size_t)(bn + rr) * OUTC + cc);
    }
    __syncthreads();

    int m2 = tid >> 1;
    int ch = (tid & 1) * 8;
    float acc2[8];
#pragma unroll
    for (int c = 0; c < 8; c++) acc2[c] = (blockIdx.y == 0) ? b2[ch + c] : 0.f;
#pragma unroll 8
    for (int k = 0; k < BN; k++) {
        float v = tile[m2 * 65 + k];
        float4 w0 = *(float4*)(W2s + k * OUTC + ch);
        float4 w1 = *(float4*)(W2s + k * OUTC + ch + 4);
        acc2[0] += v * w0.x; acc2[1] += v * w0.y;
        acc2[2] += v * w0.z; acc2[3] += v * w0.w;
        acc2[4] += v * w1.x; acc2[5] += v * w1.y;
        acc2[6] += v * w1.z; acc2[7] += v * w1.w;
    }
    int gm2 = bm + m2;
    if (gm2 < NODES) {
        red_add_f4(g_h0 + (size_t)gm2 * OUTC + ch,
                   make_float4(acc2[0], acc2[1], acc2[2], acc2[3]));
        red_add_f4(g_h0 + (size_t)gm2 * OUTC + ch + 4,
                   make_float4(acc2[4], acc2[5], acc2[6], acc2[7]));
    }
}

// ---------------- propagation: warp-per-node CSR gather, fp16 h', unroll x4 ----------------
// lane = e_local*4 + q. Batch: 4 independent csrc loads (e, e+8, e+16, e+24) then
// 4 independent 8B row loads (4 fp16 channels) -> fp32 accumulate.
// Reduce via shfl_xor(4,8,16). o = 0.9*di*(sum + h'[i]) + 0.1*h0[i].
__global__ __launch_bounds__(256) void gather_kernel(int sin, int sout, int final_,
                                                     float* __restrict__ out) {
    int w = (blockIdx.x * blockDim.x + threadIdx.x) >> 5;   // node id
    if (w >= NODES) return;
    const int lane = threadIdx.x & 31;
    const int el   = lane >> 2;    // 0..7  edge slot
    const int q    = lane & 3;     // 0..3  channel quad
    const uint2* __restrict__ hin = sel_in(sin);
    const int* __restrict__ csrc = g_csrc;
    const int end = g_rowptr[w + 1];

    float4 a0 = make_float4(0.f, 0.f, 0.f, 0.f);
    float4 a1 = make_float4(0.f, 0.f, 0.f, 0.f);
    int e = g_rowptr[w] + el;
    for (; e + 24 < end; e += 32) {
        int s0 = __ldg(&csrc[e]);
        int s1 = __ldg(&csrc[e + 8]);
        int s2 = __ldg(&csrc[e + 16]);
        int s3 = __ldg(&csrc[e + 24]);
        uint2 u0 = hin[s0 * 4 + q];
        uint2 u1 = hin[s1 * 4 + q];
        uint2 u2 = hin[s2 * 4 + q];
        uint2 u3 = hin[s3 * 4 + q];
        float4 v0 = h4_to_f4(u0);
        float4 v1 = h4_to_f4(u1);
        float4 v2 = h4_to_f4(u2);
        float4 v3 = h4_to_f4(u3);
        a0.x += v0.x + v1.x; a0.y += v0.y + v1.y;
        a0.z += v0.z + v1.z; a0.w += v0.w + v1.w;
        a1.x += v2.x + v3.x; a1.y += v2.y + v3.y;
        a1.z += v2.z + v3.z; a1.w += v2.w + v3.w;
    }
    for (; e < end; e += 8) {
        int s = __ldg(&csrc[e]);
        float4 v = h4_to_f4(hin[s * 4 + q]);
        a0.x += v.x; a0.y += v.y; a0.z += v.z; a0.w += v.w;
    }
    float4 acc = make_float4(a0.x + a1.x, a0.y + a1.y, a0.z + a1.z, a0.w + a1.w);
    // sum the 8 edge slots (lanes with same q)
#pragma unroll
    for (int off = 4; off <= 16; off <<= 1) {
        acc.x += __shfl_xor_sync(0xFFFFFFFFu, acc.x, off);
        acc.y += __shfl_xor_sync(0xFFFFFFFFu, acc.y, off);
        acc.z += __shfl_xor_sync(0xFFFFFFFFu, acc.z, off);
        acc.w += __shfl_xor_sync(0xFFFFFFFFu, acc.w, off);
    }

    float di = g_dinv[w];
    float4 hs  = h4_to_f4(hin[w * 4 + q]);       // h'[i] (scaled self)
    float4 h0v = ((const float4*)g_h0)[w * 4 + q];
    float4 o;
    o.x = 0.9f * di * (acc.x + hs.x) + 0.1f * h0v.x;
    o.y = 0.9f * di * (acc.y + hs.y) + 0.1f * h0v.y;
    o.z = 0.9f * di * (acc.z + hs.z) + 0.1f * h0v.z;
    o.w = 0.9f * di * (acc.w + hs.w) + 0.1f * h0v.w;

    if (!final_) {
        if (el == 0)
            sel_out(sout)[w * 4 + q] =
                f4_to_h4(make_float4(di * o.x, di * o.y, di * o.z, di * o.w));
    } else {
        float m = fmaxf(fmaxf(o.x, o.y), fmaxf(o.z, o.w));
        m = fmaxf(m, __shfl_xor_sync(0xFFFFFFFFu, m, 1));
        m = fmaxf(m, __shfl_xor_sync(0xFFFFFFFFu, m, 2));
        float ssum = expf(o.x - m) + expf(o.y - m) + expf(o.z - m) + expf(o.w - m);
        ssum += __shfl_xor_sync(0xFFFFFFFFu, ssum, 1);
        ssum += __shfl_xor_sync(0xFFFFFFFFu, ssum, 2);
        float ls = logf(ssum) + m;
        if (el == 0)
            ((float4*)out)[w * 4 + q] =
                make_float4(o.x - ls, o.y - ls, o.z - ls, o.w - ls);
    }
}

// ---------------- launch ----------------
extern "C" void kernel_launch(void* const* d_in, const int* in_sizes, int n_in,
                              void* d_out, int out_size)
{
    const float* x  = (const float*)d_in[0];
    const void* ei  = d_in[1];
    const float* W1 = (const float*)d_in[2];
    const float* b1 = (const float*)d_in[3];
    const float* W2 = (const float*)d_in[4];
    const float* b2 = (const float*)d_in[5];
    float* out      = (float*)d_out;

    detect_kernel<<<1, 32>>>((const int*)ei);
    zero_kernel<<<(NODES * OUTC + 255) / 256, 256>>>();
    edge_kernel<<<(NEDGES + 255) / 256, 256>>>(ei);
    scanA_kernel<<<NSCANB, SCAN_B>>>();
    scanB_kernel<<<1, 128>>>();
    scanC_kernel<<<(NODES + 255) / 256, 256>>>();
    dinv_kernel<<<(NODES + 255) / 256, 256>>>();
    place_kernel<<<(NEDGES + 255) / 256, 256>>>();
    mlp_tc_kernel<<<dim3((NODES + BM - 1) / BM, HIDC / BN), 256>>>(x, W1, b1, W2, b2);
    prescale_kernel<<<(NODES * 4 + 255) / 256, 256>>>();

    int cur = 1;
    for (int t = 0; t < KITER; t++) {
        int nxt = (cur == 1) ? 2 : 1;
        int fin = (t == KITER - 1) ? 1 : 0;
        gather_kernel<<<(NODES * 32 + 255) / 256, 256>>>(cur, nxt, fin, out);
        cur = nxt;
    }
}

// round 12
// speedup vs baseline: 1.1274x; 1.1067x over previous
#include <cuda_runtime.h>
#include <cuda_bf16.h>
#include <math.h>

#define NODES 100000
#define NEDGES 3200000
#define INC 512
#define HIDC 256
#define OUTC 16
#define KITER 10
#define SCAN_B 1024
#define NSCANB ((NODES + SCAN_B - 1) / SCAN_B)   // 98

// ---------------- scratch (static device globals; no allocation) ----------------
__device__ __align__(16) float g_h0[NODES * OUTC];   // unscaled MLP output
__device__ __align__(16) float g_hA[NODES * OUTC];   // scaled h' ping
__device__ __align__(16) float g_hB[NODES * OUTC];   // scaled h' pong
__device__ float g_dinv[NODES];
__device__ int   g_deg[NODES];
__device__ int   g_cnt[NODES];
__device__ int   g_rexcl[NODES];
__device__ int   g_bsum[NSCANB];
__device__ int   g_boff[NSCANB];
__device__ int   g_rowptr[NODES + 1];
__device__ int   g_src[NEDGES];
__device__ int   g_dst[NEDGES];
__device__ int   g_csrc[NEDGES];       // CSR: src ids grouped by dst
__device__ int   g_is64;

__device__ __forceinline__ void red_add_f4(float* addr, float4 v) {
    asm volatile("red.global.add.v4.f32 [%0], {%1, %2, %3, %4};"
                 :: "l"(addr), "f"(v.x), "f"(v.y), "f"(v.z), "f"(v.w)
                 : "memory");
}

__device__ __forceinline__ unsigned bf2_of(float a, float b) {
    __nv_bfloat162 h = __floats2bfloat162_rn(a, b);   // low = a, high = b
    return *reinterpret_cast<unsigned*>(&h);
}

// scaled buffers (1 = hA, 2 = hB)
__device__ __forceinline__ const float4* sel_in(int s) {
    return (const float4*)(s == 1 ? g_hA : g_hB);
}
__device__ __forceinline__ float4* sel_out(int s) {
    return (float4*)(s == 1 ? g_hA : g_hB);
}

// ---------------- dtype detection for edge_index (int32 vs int64) ----------------
__global__ void detect_kernel(const int* __restrict__ ei32) {
    if (threadIdx.x == 0 && blockIdx.x == 0) {
        int s = 0;
#pragma unroll
        for (int i = 0; i < 64; i++) s |= ei32[2 * i + 1];
        g_is64 = (s == 0) ? 1 : 0;
    }
}

// ---------------- init ----------------
__global__ void zero_kernel() {
    int i = blockIdx.x * blockDim.x + threadIdx.x;
    if (i < NODES * OUTC) g_h0[i] = 0.f;
    if (i < NODES) { g_deg[i] = 0; g_cnt[i] = 0; }
}

// ---------------- edge prep ----------------
__global__ void edge_kernel(const void* __restrict__ ei) {
    int e = blockIdx.x * blockDim.x + threadIdx.x;
    if (e >= NEDGES) return;
    int s, d;
    if (g_is64) {
        const long long* p = (const long long*)ei;
        s = (int)p[e];
        d = (int)p[NEDGES + e];
    } else {
        const int* p = (const int*)ei;
        s = p[e];
        d = p[NEDGES + e];
    }
    g_src[e] = s;
    g_dst[e] = d;
    atomicAdd(&g_deg[d], 1);
}

// ---------------- exclusive scan of deg -> rowptr ----------------
__global__ __launch_bounds__(SCAN_B) void scanA_kernel() {
    __shared__ int s[SCAN_B];
    int tid = threadIdx.x;
    int i = blockIdx.x * SCAN_B + tid;
    int v = (i < NODES) ? g_deg[i] : 0;
    s[tid] = v;
    __syncthreads();
#pragma unroll
    for (int off = 1; off < SCAN_B; off <<= 1) {
        int t = (tid >= off) ? s[tid - off] : 0;
        __syncthreads();
        s[tid] += t;
        __syncthreads();
    }
    if (i < NODES) g_rexcl[i] = s[tid] - v;
    if (tid == SCAN_B - 1) g_bsum[blockIdx.x] = s[tid];
}

__global__ __launch_bounds__(128) void scanB_kernel() {
    __shared__ int s[128];
    int tid = threadIdx.x;
    int v = (tid < NSCANB) ? g_bsum[tid] : 0;
    s[tid] = v;
    __syncthreads();
#pragma unroll
    for (int off = 1; off < 128; off <<= 1) {
        int t = (tid >= off) ? s[tid - off] : 0;
        __syncthreads();
        s[tid] += t;
        __syncthreads();
    }
    if (tid < NSCANB) g_boff[tid] = s[tid] - v;   // exclusive
    if (tid == 0) g_rowptr[NODES] = NEDGES;
}

__global__ void scanC_kernel() {
    int i = blockIdx.x * blockDim.x + threadIdx.x;
    if (i >= NODES) return;
    g_rowptr[i] = g_rexcl[i] + g_boff[i >> 10];
}

__global__ void dinv_kernel() {
    int i = blockIdx.x * blockDim.x + threadIdx.x;
    if (i >= NODES) return;
    g_dinv[i] = rsqrtf((float)g_deg[i] + 1.0f);   // +1 = self loop
}

// counting-sort placement: group src by dst
__global__ void place_kernel() {
    int e = blockIdx.x * blockDim.x + threadIdx.x;
    if (e >= NEDGES) return;
    int d = g_dst[e];
    int pos = g_rowptr[d] + atomicAdd(&g_cnt[d], 1);
    g_csrc[pos] = g_src[e];
}

// h'_init = dinv * h0
__global__ void prescale_kernel() {
    int t = blockIdx.x * blockDim.x + threadIdx.x;
    if (t >= NODES * 4) return;
    float di = g_dinv[t >> 2];
    float4 h = ((const float4*)g_h0)[t];
    ((float4*)g_hA)[t] = make_float4(di * h.x, di * h.y, di * h.z, di * h.w);
}

// ---------------- fused MLP via bf16 tensor cores (m16n8k16) ----------------
// smem holds bf16 PAIRS packed along k: Xp[kpair][m], Wp[kpair][n] (32-bit each).
// Frag-load indexing is identical to the proven tf32 version with k in pair units.
#define BM 128
#define BN 64
#define BKK 32              // k elements per tile = 16 pairs
#define NKP 16              // pairs per tile
#define XS_STRIDE 136
#define WS_STRIDE 72        // 72*4B = 288B row stride, 16B-aligned for uint4 stores

__global__ __launch_bounds__(256) void mlp_tc_kernel(
    const float* __restrict__ x, const float* __restrict__ W1,
    const float* __restrict__ b1, const float* __restrict__ W2,
    const float* __restrict__ b2)
{
    __shared__ __align__(16) float sm[9344];
    unsigned* Xp = (unsigned*)sm;                   // [NKP][XS_STRIDE]
    unsigned* Wp = (unsigned*)sm + NKP * XS_STRIDE; // [NKP][WS_STRIDE]

    const int tid  = threadIdx.x;
    const int lane = tid & 31;
    const int wid  = tid >> 5;
    const int warp_m = wid >> 1;
    const int warp_n = wid & 1;
    const int bm = blockIdx.x * BM;
    const int bn = blockIdx.y * BN;
    const int gID = lane >> 2;
    const int tig = lane & 3;

    float acc[2][4][4];
#pragma unroll
    for (int mt = 0; mt < 2; mt++)
#pragma unroll
        for (int nt = 0; nt < 4; nt++)
#pragma unroll
            for (int v = 0; v < 4; v++) acc[mt][nt][v] = 0.f;

    for (int k0 = 0; k0 < INC; k0 += BKK) {
        // X tile: 4 fp32 -> 2 bf16x2 pairs per load; 1024 float4 loads
#pragma unroll
        for (int it = 0; it < 4; it++) {
            int l  = tid + it * 256;
            int r  = l & 127;             // row
            int kq = l >> 7;              // 0..7 k-quad
            int gm = bm + r;
            float4 v = make_float4(0.f, 0.f, 0.f, 0.f);
            if (gm < NODES) v = *(const float4*)(x + (size_t)gm * INC + k0 + kq * 4);
            Xp[(kq * 2 + 0) * XS_STRIDE + r] = bf2_of(v.x, v.y);
            Xp[(kq * 2 + 1) * XS_STRIDE + r] = bf2_of(v.z, v.w);
        }
        // W tile: pair along k -> each thread covers (kpair, 4 n's)
        {
            int kp = tid >> 4;            // 0..15
            int nq = tid & 15;            // 0..15 -> n quad
            const float* wr = W1 + (size_t)(k0 + 2 * kp) * HIDC + bn + nq * 4;
            float4 w0 = *(const float4*)wr;
            float4 w1 = *(const float4*)(wr + HIDC);
            uint4 t;
            t.x = bf2_of(w0.x, w1.x);
            t.y = bf2_of(w0.y, w1.y);
            t.z = bf2_of(w0.z, w1.z);
            t.w = bf2_of(w0.w, w1.w);
            *(uint4*)(Wp + kp * WS_STRIDE + nq * 4) = t;
        }
        __syncthreads();

#pragma unroll
        for (int ks = 0; ks < 2; ks++) {          // 2 x k16 per tile
            const int kb = ks * 8;                // pair offset
            unsigned a[2][4], b[4][2];
#pragma unroll
            for (int mt = 0; mt < 2; mt++) {
                int m = warp_m * 32 + mt * 16 + gID;
                a[mt][0] = Xp[(kb + tig) * XS_STRIDE + m];
                a[mt][1] = Xp[(kb + tig) * XS_STRIDE + m + 8];
                a[mt][2] = Xp[(kb + tig + 4) * XS_STRIDE + m];
                a[mt][3] = Xp[(kb + tig + 4) * XS_STRIDE + m + 8];
            }
#pragma unroll
            for (int nt = 0; nt < 4; nt++) {
                int n = warp_n * 32 + nt * 8 + gID;
                b[nt][0] = Wp[(kb + tig) * WS_STRIDE + n];
                b[nt][1] = Wp[(kb + tig + 4) * WS_STRIDE + n];
            }
#pragma unroll
            for (int mt = 0; mt < 2; mt++)
#pragma unroll
                for (int nt = 0; nt < 4; nt++) {
                    float* c = acc[mt][nt];
                    asm volatile(
                        "mma.sync.aligned.m16n8k16.row.col.f32.bf16.bf16.f32 "
                        "{%0,%1,%2,%3}, {%4,%5,%6,%7}, {%8,%9}, {%0,%1,%2,%3};"
                        : "+f"(c[0]), "+f"(c[1]), "+f"(c[2]), "+f"(c[3])
                        : "r"(a[mt][0]), "r"(a[mt][1]), "r"(a[mt][2]), "r"(a[mt][3]),
                          "r"(b[nt][0]), "r"(b[nt][1]));
                }
        }
        __syncthreads();
    }

    // epilogue: bias + relu -> smem tile [128][65]
    float* tile = sm;
    float* W2s  = sm + BM * 65;

#pragma unroll
    for (int mt = 0; mt < 2; mt++) {
        int r0 = warp_m * 32 + mt * 16 + gID;
        int r1 = r0 + 8;
#pragma unroll
        for (int nt = 0; nt < 4; nt++) {
            int c0 = warp_n * 32 + nt * 8 + 2 * tig;
            int c1 = c0 + 1;
            float bc0 = b1[bn + c0];
            float bc1 = b1[bn + c1];
            float v00 = acc[mt][nt][0] + bc0;
            float v01 = acc[mt][nt][1] + bc1;
            float v10 = acc[mt][nt][2] + bc0;
            float v11 = acc[mt][nt][3] + bc1;
            tile[r0 * 65 + c0] = v00 > 0.f ? v00 : 0.f;
            tile[r0 * 65 + c1] = v01 > 0.f ? v01 : 0.f;
            tile[r1 * 65 + c0] = v10 > 0.f ? v10 : 0.f;
            tile[r1 * 65 + c1] = v11 > 0.f ? v11 : 0.f;
        }
    }
    {
        int rr = tid >> 2;
        int cc = (tid & 3) * 4;
        *(float4*)(W2s + rr * OUTC + cc) =
            *(const float4*)(W2 + (size_t)(bn + rr) * OUTC + cc);
    }
    __syncthreads();

    int m2 = tid >> 1;
    int ch = (tid & 1) * 8;
    float acc2[8];
#pragma unroll
    for (int c = 0; c < 8; c++) acc2[c] = (blockIdx.y == 0) ? b2[ch + c] : 0.f;
#pragma unroll 8
    for (int k = 0; k < BN; k++) {
        float v = tile[m2 * 65 + k];
        float4 w0 = *(float4*)(W2s + k * OUTC + ch);
        float4 w1 = *(float4*)(W2s + k * OUTC + ch + 4);
        acc2[0] += v * w0.x; acc2[1] += v * w0.y;
        acc2[2] += v * w0.z; acc2[3] += v * w0.w;
        acc2[4] += v * w1.x; acc2[5] += v * w1.y;
        acc2[6] += v * w1.z; acc2[7] += v * w1.w;
    }
    int gm2 = bm + m2;
    if (gm2 < NODES) {
        red_add_f4(g_h0 + (size_t)gm2 * OUTC + ch,
                   make_float4(acc2[0], acc2[1], acc2[2], acc2[3]));
        red_add_f4(g_h0 + (size_t)gm2 * OUTC + ch + 4,
                   make_float4(acc2[4], acc2[5], acc2[6], acc2[7]));
    }
}

// ---------------- propagation: warp-per-node CSR gather, unroll x4 (R9 best) ----------------
__global__ __launch_bounds__(256) void gather_kernel(int sin, int sout, int final_,
                                                     float* __restrict__ out) {
    int w = (blockIdx.x * blockDim.x + threadIdx.x) >> 5;   // node id
    if (w >= NODES) return;
    const int lane = threadIdx.x & 31;
    const int el   = lane >> 2;    // 0..7  edge slot
    const int q    = lane & 3;     // 0..3  channel quad
    const float4* __restrict__ hin = sel_in(sin);
    const int* __restrict__ csrc = g_csrc;
    const int end = g_rowptr[w + 1];

    float4 a0 = make_float4(0.f, 0.f, 0.f, 0.f);
    float4 a1 = make_float4(0.f, 0.f, 0.f, 0.f);
    int e = g_rowptr[w] + el;
    for (; e + 24 < end; e += 32) {
        int s0 = __ldg(&csrc[e]);
        int s1 = __ldg(&csrc[e + 8]);
        int s2 = __ldg(&csrc[e + 16]);
        int s3 = __ldg(&csrc[e + 24]);
        float4 v0 = hin[s0 * 4 + q];
        float4 v1 = hin[s1 * 4 + q];
        float4 v2 = hin[s2 * 4 + q];
        float4 v3 = hin[s3 * 4 + q];
        a0.x += v0.x + v1.x; a0.y += v0.y + v1.y;
        a0.z += v0.z + v1.z; a0.w += v0.w + v1.w;
        a1.x += v2.x + v3.x; a1.y += v2.y + v3.y;
        a1.z += v2.z + v3.z; a1.w += v2.w + v3.w;
    }
    for (; e < end; e += 8) {
        int s = __ldg(&csrc[e]);
        float4 v = hin[s * 4 + q];
        a0.x += v.x; a0.y += v.y; a0.z += v.z; a0.w += v.w;
    }
    float4 acc = make_float4(a0.x + a1.x, a0.y + a1.y, a0.z + a1.z, a0.w + a1.w);
#pragma unroll
    for (int off = 4; off <= 16; off <<= 1) {
        acc.x += __shfl_xor_sync(0xFFFFFFFFu, acc.x, off);
        acc.y += __shfl_xor_sync(0xFFFFFFFFu, acc.y, off);
        acc.z += __shfl_xor_sync(0xFFFFFFFFu, acc.z, off);
        acc.w += __shfl_xor_sync(0xFFFFFFFFu, acc.w, off);
    }

    float di = g_dinv[w];
    float4 hs  = hin[w * 4 + q];                 // h'[i] (scaled self)
    float4 h0v = ((const float4*)g_h0)[w * 4 + q];
    float4 o;
    o.x = 0.9f * di * (acc.x + hs.x) + 0.1f * h0v.x;
    o.y = 0.9f * di * (acc.y + hs.y) + 0.1f * h0v.y;
    o.z = 0.9f * di * (acc.z + hs.z) + 0.1f * h0v.z;
    o.w = 0.9f * di * (acc.w + hs.w) + 0.1f * h0v.w;

    if (!final_) {
        if (el == 0)
            sel_out(sout)[w * 4 + q] =
                make_float4(di * o.x, di * o.y, di * o.z, di * o.w);
    } else {
        float m = fmaxf(fmaxf(o.x, o.y), fmaxf(o.z, o.w));
        m = fmaxf(m, __shfl_xor_sync(0xFFFFFFFFu, m, 1));
        m = fmaxf(m, __shfl_xor_sync(0xFFFFFFFFu, m, 2));
        float ssum = expf(o.x - m) + expf(o.y - m) + expf(o.z - m) + expf(o.w - m);
        ssum += __shfl_xor_sync(0xFFFFFFFFu, ssum, 1);
        ssum += __shfl_xor_sync(0xFFFFFFFFu, ssum, 2);
        float ls = logf(ssum) + m;
        if (el == 0)
            ((float4*)out)[w * 4 + q] =
                make_float4(o.x - ls, o.y - ls, o.z - ls, o.w - ls);
    }
}

// ---------------- launch ----------------
extern "C" void kernel_launch(void* const* d_in, const int* in_sizes, int n_in,
                              void* d_out, int out_size)
{
    const float* x  = (const float*)d_in[0];
    const void* ei  = d_in[1];
    const float* W1 = (const float*)d_in[2];
    const float* b1 = (const float*)d_in[3];
    const float* W2 = (const float*)d_in[4];
    const float* b2 = (const float*)d_in[5];
    float* out      = (float*)d_out;

    detect_kernel<<<1, 32>>>((const int*)ei);                           // 1
    zero_kernel<<<(NODES * OUTC + 255) / 256, 256>>>();                 // 2
    edge_kernel<<<(NEDGES + 255) / 256, 256>>>(ei);                     // 3
    mlp_tc_kernel<<<dim3((NODES + BM - 1) / BM, HIDC / BN), 256>>>(     // 4 <- profiled
        x, W1, b1, W2, b2);
    scanA_kernel<<<NSCANB, SCAN_B>>>();
    scanB_kernel<<<1, 128>>>();
    scanC_kernel<<<(NODES + 255) / 256, 256>>>();
    dinv_kernel<<<(NODES + 255) / 256, 256>>>();
    place_kernel<<<(NEDGES + 255) / 256, 256>>>();
    prescale_kernel<<<(NODES * 4 + 255) / 256, 256>>>();

    int cur = 1;
    for (int t = 0; t < KITER; t++) {
        int nxt = (cur == 1) ? 2 : 1;
        int fin = (t == KITER - 1) ? 1 : 0;
        gather_kernel<<<(NODES * 32 + 255) / 256, 256>>>(cur, nxt, fin, out);
        cur = nxt;
    }
}

// round 13
// speedup vs baseline: 1.1461x; 1.0166x over previous
#include <cuda_runtime.h>
#include <cuda_bf16.h>
#include <math.h>

#define NODES 100000
#define NEDGES 3200000
#define INC 512
#define HIDC 256
#define OUTC 16
#define KITER 10
#define SCAN_B 1024
#define NSCANB ((NODES + SCAN_B - 1) / SCAN_B)   // 98

// ---------------- scratch (static device globals; no allocation) ----------------
__device__ __align__(16) float g_h0[NODES * OUTC];   // unscaled MLP output
__device__ __align__(16) float g_hA[NODES * OUTC];   // scaled h' ping
__device__ __align__(16) float g_hB[NODES * OUTC];   // scaled h' pong
__device__ float g_dinv[NODES];
__device__ int   g_deg[NODES];
__device__ int   g_cnt[NODES];
__device__ int   g_rexcl[NODES];
__device__ int   g_bsum[NSCANB];
__device__ int   g_boff[NSCANB];
__device__ int   g_rowptr[NODES + 1];
__device__ int   g_src[NEDGES];
__device__ int   g_dst[NEDGES];
__device__ int   g_csrc[NEDGES];       // CSR: src ids grouped by dst
__device__ int   g_is64;

__device__ __forceinline__ void red_add_f4(float* addr, float4 v) {
    asm volatile("red.global.add.v4.f32 [%0], {%1, %2, %3, %4};"
                 :: "l"(addr), "f"(v.x), "f"(v.y), "f"(v.z), "f"(v.w)
                 : "memory");
}

__device__ __forceinline__ unsigned bf2_of(float a, float b) {
    __nv_bfloat162 h = __floats2bfloat162_rn(a, b);   // low = a, high = b
    return *reinterpret_cast<unsigned*>(&h);
}

// scaled buffers (1 = hA, 2 = hB)
__device__ __forceinline__ const float4* sel_in(int s) {
    return (const float4*)(s == 1 ? g_hA : g_hB);
}
__device__ __forceinline__ float4* sel_out(int s) {
    return (float4*)(s == 1 ? g_hA : g_hB);
}

// ---------------- dtype detection for edge_index (int32 vs int64) ----------------
__global__ void detect_kernel(const int* __restrict__ ei32) {
    if (threadIdx.x == 0 && blockIdx.x == 0) {
        int s = 0;
#pragma unroll
        for (int i = 0; i < 64; i++) s |= ei32[2 * i + 1];
        g_is64 = (s == 0) ? 1 : 0;
    }
}

// ---------------- init ----------------
__global__ void zero_kernel() {
    int i = blockIdx.x * blockDim.x + threadIdx.x;
    if (i < NODES * OUTC) g_h0[i] = 0.f;
    if (i < NODES) { g_deg[i] = 0; g_cnt[i] = 0; }
}

// ---------------- edge prep ----------------
__global__ void edge_kernel(const void* __restrict__ ei) {
    int e = blockIdx.x * blockDim.x + threadIdx.x;
    if (e >= NEDGES) return;
    int s, d;
    if (g_is64) {
        const long long* p = (const long long*)ei;
        s = (int)p[e];
        d = (int)p[NEDGES + e];
    } else {
        const int* p = (const int*)ei;
        s = p[e];
        d = p[NEDGES + e];
    }
    g_src[e] = s;
    g_dst[e] = d;
    atomicAdd(&g_deg[d], 1);
}

// ---------------- exclusive scan of deg -> rowptr ----------------
__global__ __launch_bounds__(SCAN_B) void scanA_kernel() {
    __shared__ int s[SCAN_B];
    int tid = threadIdx.x;
    int i = blockIdx.x * SCAN_B + tid;
    int v = (i < NODES) ? g_deg[i] : 0;
    s[tid] = v;
    __syncthreads();
#pragma unroll
    for (int off = 1; off < SCAN_B; off <<= 1) {
        int t = (tid >= off) ? s[tid - off] : 0;
        __syncthreads();
        s[tid] += t;
        __syncthreads();
    }
    if (i < NODES) g_rexcl[i] = s[tid] - v;
    if (tid == SCAN_B - 1) g_bsum[blockIdx.x] = s[tid];
}

__global__ __launch_bounds__(128) void scanB_kernel() {
    __shared__ int s[128];
    int tid = threadIdx.x;
    int v = (tid < NSCANB) ? g_bsum[tid] : 0;
    s[tid] = v;
    __syncthreads();
#pragma unroll
    for (int off = 1; off < 128; off <<= 1) {
        int t = (tid >= off) ? s[tid - off] : 0;
        __syncthreads();
        s[tid] += t;
        __syncthreads();
    }
    if (tid < NSCANB) g_boff[tid] = s[tid] - v;   // exclusive
    if (tid == 0) g_rowptr[NODES] = NEDGES;
}

__global__ void scanC_kernel() {
    int i = blockIdx.x * blockDim.x + threadIdx.x;
    if (i >= NODES) return;
    g_rowptr[i] = g_rexcl[i] + g_boff[i >> 10];
}

__global__ void dinv_kernel() {
    int i = blockIdx.x * blockDim.x + threadIdx.x;
    if (i >= NODES) return;
    g_dinv[i] = rsqrtf((float)g_deg[i] + 1.0f);   // +1 = self loop
}

// counting-sort placement: group src by dst
__global__ void place_kernel() {
    int e = blockIdx.x * blockDim.x + threadIdx.x;
    if (e >= NEDGES) return;
    int d = g_dst[e];
    int pos = g_rowptr[d] + atomicAdd(&g_cnt[d], 1);
    g_csrc[pos] = g_src[e];
}

// h'_init = dinv * h0
__global__ void prescale_kernel() {
    int t = blockIdx.x * blockDim.x + threadIdx.x;
    if (t >= NODES * 4) return;
    float di = g_dinv[t >> 2];
    float4 h = ((const float4*)g_h0)[t];
    ((float4*)g_hA)[t] = make_float4(di * h.x, di * h.y, di * h.z, di * h.w);
}

// ---------------- fused MLP via bf16 tensor cores (m16n8k16) ----------------
// Grid is (n-blocks, m-blocks): the 4 CTAs sharing an X tile are CONSECUTIVE
// bids -> co-scheduled -> 3 of 4 X-tile reads hit L2 (was 4x DRAM traffic).
#define BM 128
#define BN 64
#define BKK 32              // k elements per tile = 16 pairs
#define NKP 16              // pairs per tile
#define XS_STRIDE 136
#define WS_STRIDE 72        // 72*4B = 288B row stride, 16B-aligned for uint4 stores

__global__ __launch_bounds__(256) void mlp_tc_kernel(
    const float* __restrict__ x, const float* __restrict__ W1,
    const float* __restrict__ b1, const float* __restrict__ W2,
    const float* __restrict__ b2)
{
    __shared__ __align__(16) float sm[9344];
    unsigned* Xp = (unsigned*)sm;                   // [NKP][XS_STRIDE]
    unsigned* Wp = (unsigned*)sm + NKP * XS_STRIDE; // [NKP][WS_STRIDE]

    const int tid  = threadIdx.x;
    const int lane = tid & 31;
    const int wid  = tid >> 5;
    const int warp_m = wid >> 1;
    const int warp_n = wid & 1;
    const int bm = blockIdx.y * BM;      // m-block on slow axis
    const int bn = blockIdx.x * BN;      // n-block on fast axis (L2 reuse of X)
    const int gID = lane >> 2;
    const int tig = lane & 3;

    float acc[2][4][4];
#pragma unroll
    for (int mt = 0; mt < 2; mt++)
#pragma unroll
        for (int nt = 0; nt < 4; nt++)
#pragma unroll
            for (int v = 0; v < 4; v++) acc[mt][nt][v] = 0.f;

    for (int k0 = 0; k0 < INC; k0 += BKK) {
        // X tile: 4 fp32 -> 2 bf16x2 pairs per load; 1024 float4 loads
#pragma unroll
        for (int it = 0; it < 4; it++) {
            int l  = tid + it * 256;
            int r  = l & 127;             // row
            int kq = l >> 7;              // 0..7 k-quad
            int gm = bm + r;
            float4 v = make_float4(0.f, 0.f, 0.f, 0.f);
            if (gm < NODES) v = *(const float4*)(x + (size_t)gm * INC + k0 + kq * 4);
            Xp[(kq * 2 + 0) * XS_STRIDE + r] = bf2_of(v.x, v.y);
            Xp[(kq * 2 + 1) * XS_STRIDE + r] = bf2_of(v.z, v.w);
        }
        // W tile: pair along k -> each thread covers (kpair, 4 n's)
        {
            int kp = tid >> 4;            // 0..15
            int nq = tid & 15;            // 0..15 -> n quad
            const float* wr = W1 + (size_t)(k0 + 2 * kp) * HIDC + bn + nq * 4;
            float4 w0 = *(const float4*)wr;
            float4 w1 = *(const float4*)(wr + HIDC);
            uint4 t;
            t.x = bf2_of(w0.x, w1.x);
            t.y = bf2_of(w0.y, w1.y);
            t.z = bf2_of(w0.z, w1.z);
            t.w = bf2_of(w0.w, w1.w);
            *(uint4*)(Wp + kp * WS_STRIDE + nq * 4) = t;
        }
        __syncthreads();

#pragma unroll
        for (int ks = 0; ks < 2; ks++) {          // 2 x k16 per tile
            const int kb = ks * 8;                // pair offset
            unsigned a[2][4], b[4][2];
#pragma unroll
            for (int mt = 0; mt < 2; mt++) {
                int m = warp_m * 32 + mt * 16 + gID;
                a[mt][0] = Xp[(kb + tig) * XS_STRIDE + m];
                a[mt][1] = Xp[(kb + tig) * XS_STRIDE + m + 8];
                a[mt][2] = Xp[(kb + tig + 4) * XS_STRIDE + m];
                a[mt][3] = Xp[(kb + tig + 4) * XS_STRIDE + m + 8];
            }
#pragma unroll
            for (int nt = 0; nt < 4; nt++) {
                int n = warp_n * 32 + nt * 8 + gID;
                b[nt][0] = Wp[(kb + tig) * WS_STRIDE + n];
                b[nt][1] = Wp[(kb + tig + 4) * WS_STRIDE + n];
            }
#pragma unroll
            for (int mt = 0; mt < 2; mt++)
#pragma unroll
                for (int nt = 0; nt < 4; nt++) {
                    float* c = acc[mt][nt];
                    asm volatile(
                        "mma.sync.aligned.m16n8k16.row.col.f32.bf16.bf16.f32 "
                        "{%0,%1,%2,%3}, {%4,%5,%6,%7}, {%8,%9}, {%0,%1,%2,%3};"
                        : "+f"(c[0]), "+f"(c[1]), "+f"(c[2]), "+f"(c[3])
                        : "r"(a[mt][0]), "r"(a[mt][1]), "r"(a[mt][2]), "r"(a[mt][3]),
                          "r"(b[nt][0]), "r"(b[nt][1]));
                }
        }
        __syncthreads();
    }

    // epilogue: bias + relu -> smem tile [128][65]
    float* tile = sm;
    float* W2s  = sm + BM * 65;

#pragma unroll
    for (int mt = 0; mt < 2; mt++) {
        int r0 = warp_m * 32 + mt * 16 + gID;
        int r1 = r0 + 8;
#pragma unroll
        for (int nt = 0; nt < 4; nt++) {
            int c0 = warp_n * 32 + nt * 8 + 2 * tig;
            int c1 = c0 + 1;
            float bc0 = b1[bn + c0];
            float bc1 = b1[bn + c1];
            float v00 = acc[mt][nt][0] + bc0;
            float v01 = acc[mt][nt][1] + bc1;
            float v10 = acc[mt][nt][2] + bc0;
            float v11 = acc[mt][nt][3] + bc1;
            tile[r0 * 65 + c0] = v00 > 0.f ? v00 : 0.f;
            tile[r0 * 65 + c1] = v01 > 0.f ? v01 : 0.f;
            tile[r1 * 65 + c0] = v10 > 0.f ? v10 : 0.f;
            tile[r1 * 65 + c1] = v11 > 0.f ? v11 : 0.f;
        }
    }
    {
        int rr = tid >> 2;
        int cc = (tid & 3) * 4;
        *(float4*)(W2s + rr * OUTC + cc) =
            *(const float4*)(W2 + (size_t)(bn + rr) * OUTC + cc);
    }
    __syncthreads();

    int m2 = tid >> 1;
    int ch = (tid & 1) * 8;
    float acc2[8];
#pragma unroll
    for (int c = 0; c < 8; c++) acc2[c] = (blockIdx.x == 0) ? b2[ch + c] : 0.f;
#pragma unroll 8
    for (int k = 0; k < BN; k++) {
        float v = tile[m2 * 65 + k];
        float4 w0 = *(float4*)(W2s + k * OUTC + ch);
        float4 w1 = *(float4*)(W2s + k * OUTC + ch + 4);
        acc2[0] += v * w0.x; acc2[1] += v * w0.y;
        acc2[2] += v * w0.z; acc2[3] += v * w0.w;
        acc2[4] += v * w1.x; acc2[5] += v * w1.y;
        acc2[6] += v * w1.z; acc2[7] += v * w1.w;
    }
    int gm2 = bm + m2;
    if (gm2 < NODES) {
        red_add_f4(g_h0 + (size_t)gm2 * OUTC + ch,
                   make_float4(acc2[0], acc2[1], acc2[2], acc2[3]));
        red_add_f4(g_h0 + (size_t)gm2 * OUTC + ch + 4,
                   make_float4(acc2[4], acc2[5], acc2[6], acc2[7]));
    }
}

// ---------------- propagation: warp-per-node CSR gather, unroll x4 (R9 best) ----------------
__global__ __launch_bounds__(256) void gather_kernel(int sin, int sout, int final_,
                                                     float* __restrict__ out) {
    int w = (blockIdx.x * blockDim.x + threadIdx.x) >> 5;   // node id
    if (w >= NODES) return;
    const int lane = threadIdx.x & 31;
    const int el   = lane >> 2;    // 0..7  edge slot
    const int q    = lane & 3;     // 0..3  channel quad
    const float4* __restrict__ hin = sel_in(sin);
    const int* __restrict__ csrc = g_csrc;
    const int end = g_rowptr[w + 1];

    float4 a0 = make_float4(0.f, 0.f, 0.f, 0.f);
    float4 a1 = make_float4(0.f, 0.f, 0.f, 0.f);
    int e = g_rowptr[w] + el;
    for (; e + 24 < end; e += 32) {
        int s0 = __ldg(&csrc[e]);
        int s1 = __ldg(&csrc[e + 8]);
        int s2 = __ldg(&csrc[e + 16]);
        int s3 = __ldg(&csrc[e + 24]);
        float4 v0 = hin[s0 * 4 + q];
        float4 v1 = hin[s1 * 4 + q];
        float4 v2 = hin[s2 * 4 + q];
        float4 v3 = hin[s3 * 4 + q];
        a0.x += v0.x + v1.x; a0.y += v0.y + v1.y;
        a0.z += v0.z + v1.z; a0.w += v0.w + v1.w;
        a1.x += v2.x + v3.x; a1.y += v2.y + v3.y;
        a1.z += v2.z + v3.z; a1.w += v2.w + v3.w;
    }
    for (; e < end; e += 8) {
        int s = __ldg(&csrc[e]);
        float4 v = hin[s * 4 + q];
        a0.x += v.x; a0.y += v.y; a0.z += v.z; a0.w += v.w;
    }
    float4 acc = make_float4(a0.x + a1.x, a0.y + a1.y, a0.z + a1.z, a0.w + a1.w);
#pragma unroll
    for (int off = 4; off <= 16; off <<= 1) {
        acc.x += __shfl_xor_sync(0xFFFFFFFFu, acc.x, off);
        acc.y += __shfl_xor_sync(0xFFFFFFFFu, acc.y, off);
        acc.z += __shfl_xor_sync(0xFFFFFFFFu, acc.z, off);
        acc.w += __shfl_xor_sync(0xFFFFFFFFu, acc.w, off);
    }

    float di = g_dinv[w];
    float4 hs  = hin[w * 4 + q];                 // h'[i] (scaled self)
    float4 h0v = ((const float4*)g_h0)[w * 4 + q];
    float4 o;
    o.x = 0.9f * di * (acc.x + hs.x) + 0.1f * h0v.x;
    o.y = 0.9f * di * (acc.y + hs.y) + 0.1f * h0v.y;
    o.z = 0.9f * di * (acc.z + hs.z) + 0.1f * h0v.z;
    o.w = 0.9f * di * (acc.w + hs.w) + 0.1f * h0v.w;

    if (!final_) {
        if (el == 0)
            sel_out(sout)[w * 4 + q] =
                make_float4(di * o.x, di * o.y, di * o.z, di * o.w);
    } else {
        float m = fmaxf(fmaxf(o.x, o.y), fmaxf(o.z, o.w));
        m = fmaxf(m, __shfl_xor_sync(0xFFFFFFFFu, m, 1));
        m = fmaxf(m, __shfl_xor_sync(0xFFFFFFFFu, m, 2));
        float ssum = expf(o.x - m) + expf(o.y - m) + expf(o.z - m) + expf(o.w - m);
        ssum += __shfl_xor_sync(0xFFFFFFFFu, ssum, 1);
        ssum += __shfl_xor_sync(0xFFFFFFFFu, ssum, 2);
        float ls = logf(ssum) + m;
        if (el == 0)
            ((float4*)out)[w * 4 + q] =
                make_float4(o.x - ls, o.y - ls, o.z - ls, o.w - ls);
    }
}

// ---------------- launch ----------------
extern "C" void kernel_launch(void* const* d_in, const int* in_sizes, int n_in,
                              void* d_out, int out_size)
{
    const float* x  = (const float*)d_in[0];
    const void* ei  = d_in[1];
    const float* W1 = (const float*)d_in[2];
    const float* b1 = (const float*)d_in[3];
    const float* W2 = (const float*)d_in[4];
    const float* b2 = (const float*)d_in[5];
    float* out      = (float*)d_out;

    detect_kernel<<<1, 32>>>((const int*)ei);                           // 1
    zero_kernel<<<(NODES * OUTC + 255) / 256, 256>>>();                 // 2
    edge_kernel<<<(NEDGES + 255) / 256, 256>>>(ei);                     // 3
    mlp_tc_kernel<<<dim3(HIDC / BN, (NODES + BM - 1) / BM), 256>>>(     // 4 <- profiled
        x, W1, b1, W2, b2);
    scanA_kernel<<<NSCANB, SCAN_B>>>();
    scanB_kernel<<<1, 128>>>();
    scanC_kernel<<<(NODES + 255) / 256, 256>>>();
    dinv_kernel<<<(NODES + 255) / 256, 256>>>();
    place_kernel<<<(NEDGES + 255) / 256, 256>>>();
    prescale_kernel<<<(NODES * 4 + 255) / 256, 256>>>();

    int cur = 1;
    for (int t = 0; t < KITER; t++) {
        int nxt = (cur == 1) ? 2 : 1;
        int fin = (t == KITER - 1) ? 1 : 0;
        gather_kernel<<<(NODES * 32 + 255) / 256, 256>>>(cur, nxt, fin, out);
        cur = nxt;
    }
}